// round 4
// baseline (speedup 1.0000x reference)
#include <cuda_runtime.h>
#include <cuda_fp16.h>
#include <cuda_bf16.h>
#include <stdint.h>

// Problem dims (fixed)
#define BB 4096   // batch
#define DD 2048   // input dim
#define LL 16384  // latent dim
#define KK 64     // topk
#define CAND_MAX 512

// ---------------- scratch (static device globals) ---------------------------
__device__ float         g_Wt[(size_t)LL * DD];    // W^T fp32 [L, D] (recompute/decode)
__device__ __nv_bfloat16 g_WB[(size_t)DD * LL];    // W bf16  [D, L] (GEMM B, k-major)
__device__ __nv_bfloat16 g_XB[(size_t)BB * DD];    // X bf16  [B, D]
__device__ __half        g_Zh[(size_t)BB * LL];    // |z_approx| half [B, L]

// ---------------- mma.sync helpers (plain sm_80+ PTX) ------------------------
__device__ __forceinline__ void cp16(uint32_t dst, const void* src) {
    asm volatile("cp.async.cg.shared.global [%0], [%1], 16;\n" :: "r"(dst), "l"(src));
}

__device__ __forceinline__ void ldsm_x4(uint32_t* r, uint32_t addr) {
    asm volatile("ldmatrix.sync.aligned.m8n8.x4.shared.b16 {%0,%1,%2,%3}, [%4];"
                 : "=r"(r[0]), "=r"(r[1]), "=r"(r[2]), "=r"(r[3]) : "r"(addr));
}

__device__ __forceinline__ void ldsm_x4_t(uint32_t* r, uint32_t addr) {
    asm volatile("ldmatrix.sync.aligned.m8n8.x4.trans.shared.b16 {%0,%1,%2,%3}, [%4];"
                 : "=r"(r[0]), "=r"(r[1]), "=r"(r[2]), "=r"(r[3]) : "r"(addr));
}

__device__ __forceinline__ void mma16816(float* c, const uint32_t* a, const uint32_t* b) {
    asm volatile(
        "mma.sync.aligned.m16n8k16.row.col.f32.bf16.bf16.f32 "
        "{%0,%1,%2,%3}, {%4,%5,%6,%7}, {%8,%9}, {%0,%1,%2,%3};"
        : "+f"(c[0]), "+f"(c[1]), "+f"(c[2]), "+f"(c[3])
        : "r"(a[0]), "r"(a[1]), "r"(a[2]), "r"(a[3]), "r"(b[0]), "r"(b[1]));
}

// ---------------- W transpose (fp32) + bf16 copy of W ------------------------
__global__ void transpose_kernel(const float* __restrict__ W) {
    __shared__ float tile[32][33];
    int l0 = blockIdx.x * 32;
    int d0 = blockIdx.y * 32;
    int tx = threadIdx.x;      // 0..31
    int ty = threadIdx.y;      // 0..7
    #pragma unroll
    for (int r = ty; r < 32; r += 8) {
        size_t src = (size_t)(d0 + r) * LL + (l0 + tx);
        float v = W[src];
        tile[r][tx] = v;
        g_WB[src] = __float2bfloat16(v);   // bf16 copy, same layout, coalesced
    }
    __syncthreads();
    #pragma unroll
    for (int r = ty; r < 32; r += 8)
        g_Wt[(size_t)(l0 + r) * DD + (d0 + tx)] = tile[tx][r];
}

// ---------------- X -> bf16 ---------------------------------------------------
__global__ __launch_bounds__(256) void convert_x_kernel(const float* __restrict__ X) {
    size_t i = (size_t)blockIdx.x * 256 + threadIdx.x;   // over BB*DD/4 float4s
    float4 v = ((const float4*)X)[i];
    __nv_bfloat16 o[4];
    o[0] = __float2bfloat16(v.x);
    o[1] = __float2bfloat16(v.y);
    o[2] = __float2bfloat16(v.z);
    o[3] = __float2bfloat16(v.w);
    *(uint2*)(&g_XB[i * 4]) = *(uint2*)o;
}

// ---------------- encode GEMM via mma.sync bf16 ------------------------------
// Z[B,L] = X[B,D] @ W[D,L]; block tile 128x256, BK=32, 4-stage, warp tile 64x64.
#define BM 128
#define BN 256
#define BK 32
#define STG 4
#define ASTRIDE 40                  // bf16 elems per A smem row (pad 32->40)
#define BSTRIDE 264                 // bf16 elems per B smem row (pad 256->264)
#define ASTG_B (BM * ASTRIDE * 2)   // 10240 B
#define BSTG_B (BK * BSTRIDE * 2)   // 16896 B
#define GEMM_SMEM (STG * (ASTG_B + BSTG_B) + 1024 + 256)

__global__ __launch_bounds__(256) void encode_gemm_mma(const float* __restrict__ benc) {
    extern __shared__ unsigned char dynsm[];
    const uint32_t sbase = (uint32_t)__cvta_generic_to_shared(dynsm);
    const uint32_t sA = sbase;
    const uint32_t sB = sbase + STG * ASTG_B;
    float* sbias = (float*)(dynsm + STG * (ASTG_B + BSTG_B));

    const int tid = threadIdx.x;
    const int lane = tid & 31;
    const int wid = tid >> 5;
    const int warp_m = wid & 1;      // 0..1 -> 64 rows each
    const int warp_n = wid >> 1;     // 0..3 -> 64 cols each
    const int row0 = blockIdx.x * BM;
    const int n0   = blockIdx.y * BN;

    sbias[tid] = benc[n0 + tid];     // 256 threads, 256 cols

    // ldmatrix per-lane offsets
    const int a_r = lane & 15;                 // row within 16
    const int a_k = (lane >> 4) << 3;          // k offset 0/8
    const int b_k = (lane & 7) + ((lane >> 3) & 1) * 8;  // k row 0..15
    const int b_n = (lane >> 4) << 3;          // n offset 0/8

    auto load_stage = [&](int s, int buf) {
        const int k0 = s * BK;
        #pragma unroll
        for (int c = tid; c < 512; c += 256) {       // A: 128 rows x 4 chunks of 8
            int r = c >> 2, col = (c & 3) * 8;
            cp16(sA + buf * ASTG_B + r * (ASTRIDE * 2) + col * 2,
                 g_XB + (size_t)(row0 + r) * DD + k0 + col);
        }
        #pragma unroll
        for (int c = tid; c < 1024; c += 256) {      // B: 32 rows x 32 chunks of 8
            int r = c >> 5, col = (c & 31) * 8;
            cp16(sB + buf * BSTG_B + r * (BSTRIDE * 2) + col * 2,
                 g_WB + (size_t)(k0 + r) * LL + n0 + col);
        }
    };

    #pragma unroll
    for (int s = 0; s < STG; s++) {
        load_stage(s, s);
        asm volatile("cp.async.commit_group;" ::: "memory");
    }

    float acc[4][8][4];
    #pragma unroll
    for (int i = 0; i < 4; i++)
        #pragma unroll
        for (int j = 0; j < 8; j++)
            #pragma unroll
            for (int q = 0; q < 4; q++) acc[i][j][q] = 0.0f;

    const int NST = DD / BK;   // 64
    for (int s = 0; s < NST; s++) {
        asm volatile("cp.async.wait_group %0;" :: "n"(STG - 1) : "memory");
        __syncthreads();
        const int buf = s % STG;
        const uint32_t a_base = sA + buf * ASTG_B;
        const uint32_t b_base = sB + buf * BSTG_B;

        #pragma unroll
        for (int kk = 0; kk < BK; kk += 16) {
            uint32_t a[4][4], bq[4][4];
            #pragma unroll
            for (int i = 0; i < 4; i++)
                ldsm_x4(a[i], a_base + (warp_m * 64 + i * 16 + a_r) * (ASTRIDE * 2)
                              + (kk + a_k) * 2);
            #pragma unroll
            for (int j = 0; j < 4; j++)
                ldsm_x4_t(bq[j], b_base + (kk + b_k) * (BSTRIDE * 2)
                                + (warp_n * 64 + j * 16 + b_n) * 2);
            #pragma unroll
            for (int i = 0; i < 4; i++)
                #pragma unroll
                for (int j = 0; j < 8; j++)
                    mma16816(acc[i][j], a[i], &bq[j >> 1][(j & 1) * 2]);
        }
        __syncthreads();
        if (s + STG < NST) load_stage(s + STG, buf);
        asm volatile("cp.async.commit_group;" ::: "memory");
    }

    // epilogue: z = acc + bias; store |z| as half
    #pragma unroll
    for (int i = 0; i < 4; i++) {
        const int r_lo = row0 + warp_m * 64 + i * 16 + (lane >> 2);
        #pragma unroll
        for (int j = 0; j < 8; j++) {
            const int cl = warp_n * 64 + j * 8 + (lane & 3) * 2;
            float z0 = fabsf(acc[i][j][0] + sbias[cl]);
            float z1 = fabsf(acc[i][j][1] + sbias[cl + 1]);
            float z2 = fabsf(acc[i][j][2] + sbias[cl]);
            float z3 = fabsf(acc[i][j][3] + sbias[cl + 1]);
            *(__half2*)(g_Zh + (size_t)r_lo * LL + n0 + cl)       = __floats2half2_rn(z0, z1);
            *(__half2*)(g_Zh + (size_t)(r_lo + 8) * LL + n0 + cl) = __floats2half2_rn(z2, z3);
        }
    }
}

// ---------------- finalize: select + exact recompute + topk + decode ---------
// One block per row.
__global__ __launch_bounds__(256) void finalize_kernel(
    const float* __restrict__ X, const float* __restrict__ benc,
    const float* __restrict__ bdec, float* __restrict__ Zs,
    float* __restrict__ R)
{
    __shared__ unsigned short keys[LL];     // 32 KB
    __shared__ float sx[DD];                // 8 KB
    __shared__ float sval[CAND_MAX];
    __shared__ int   scid[CAND_MAX];
    __shared__ float sv64[KK];
    __shared__ int   si64[KK];
    __shared__ int   hist[256];
    __shared__ int   s_h, s_rem, s_ctk, s_cnt, s_pos;

    const int row = blockIdx.x;
    const int tid = threadIdx.x;
    const int lid = tid & 31, wid = tid >> 5;

    // load |z| keys + x row
    const __half* zr = g_Zh + (size_t)row * LL;
    #pragma unroll
    for (int i = 0; i < 8; i++) {
        int v4 = tid + i * 256;
        ((uint4*)keys)[v4] = ((const uint4*)zr)[v4];
    }
    for (int i = tid; i < DD / 4; i += 256)
        ((float4*)sx)[i] = ((const float4*)(X + (size_t)row * DD))[i];
    if (tid == 0) { s_cnt = 0; s_pos = 0; }
    hist[tid] = 0;
    __syncthreads();

    // radix pass 1: high byte
    for (int i = 0; i < 64; i++) {
        unsigned k = keys[tid + i * 256];
        atomicAdd(&hist[k >> 8], 1);
    }
    __syncthreads();
    if (tid == 0) {
        int r = KK;
        for (int b = 255; b >= 0; b--) {
            int c = hist[b];
            if (c >= r) { s_h = b; s_rem = r; break; }
            r -= c;
        }
    }
    __syncthreads();
    const unsigned hb = (unsigned)s_h;
    hist[tid] = 0;
    __syncthreads();

    // radix pass 2: low byte
    for (int i = 0; i < 64; i++) {
        unsigned k = keys[tid + i * 256];
        if ((k >> 8) == hb) atomicAdd(&hist[k & 255], 1);
    }
    __syncthreads();
    if (tid == 0) {
        int r = s_rem; int lo = 0;
        for (int b = 255; b >= 0; b--) {
            int c = hist[b];
            if (c >= r) { lo = b; break; }
            r -= c;
        }
        unsigned short t64 = (unsigned short)((hb << 8) | (unsigned)lo);
        float tf = __half2float(__ushort_as_half(t64));
        float thr = fmaxf(tf - 0.09f, 0.0f);     // margin >> bf16 GEMM noise
        s_ctk = (int)(unsigned)__half_as_ushort(__float2half_rd(thr));
    }
    __syncthreads();
    const unsigned ctk = (unsigned)s_ctk;

    // collect candidates
    for (int i = 0; i < 64; i++) {
        int idx = tid + i * 256;
        if ((unsigned)keys[idx] >= ctk) {
            int p = atomicAdd(&s_cnt, 1);
            if (p < CAND_MAX) scid[p] = idx;
        }
    }
    __syncthreads();
    const int nc = min(s_cnt, CAND_MAX);

    // exact fp32 dot per candidate (warp per candidate)
    for (int c = wid; c < nc; c += 8) {
        int idx = scid[c];
        const float* wp = g_Wt + (size_t)idx * DD;
        float acc = 0.0f;
        #pragma unroll 8
        for (int i = 0; i < DD / 32; i++)
            acc = fmaf(wp[lid + i * 32], sx[lid + i * 32], acc);
        #pragma unroll
        for (int o = 16; o > 0; o >>= 1)
            acc += __shfl_down_sync(0xffffffffu, acc, o);
        if (lid == 0) sval[c] = acc + benc[idx];
    }
    __syncthreads();

    // exact rank among candidates (|v| desc, lowest index wins on ties)
    for (int c = tid; c < nc; c += 256) {
        float v = sval[c];
        float av = fabsf(v);
        int id = scid[c];
        int rank = 0;
        for (int j = 0; j < nc; j++) {
            float aj = fabsf(sval[j]);
            if (aj > av || (aj == av && scid[j] < id)) rank++;
        }
        if (rank < KK) {
            int p = atomicAdd(&s_pos, 1);
            si64[p] = id;
            sv64[p] = v;
            Zs[(size_t)row * LL + id] = v;
        }
    }
    __syncthreads();
    const int nsel = s_pos;   // == KK when nc >= KK

    // decode: recon[row, :] = sum_j v_j * Wt[idx_j, :] + b_dec
    const int d0 = tid * 8;
    float acc[8];
    {
        float4 b0 = *(const float4*)(bdec + d0);
        float4 b1 = *(const float4*)(bdec + d0 + 4);
        acc[0]=b0.x; acc[1]=b0.y; acc[2]=b0.z; acc[3]=b0.w;
        acc[4]=b1.x; acc[5]=b1.y; acc[6]=b1.z; acc[7]=b1.w;
    }
    for (int j = 0; j < nsel; j++) {
        const float v = sv64[j];
        const float* wp = g_Wt + (size_t)si64[j] * DD + d0;
        float4 w0 = *(const float4*)(wp);
        float4 w1 = *(const float4*)(wp + 4);
        acc[0] = fmaf(v, w0.x, acc[0]);
        acc[1] = fmaf(v, w0.y, acc[1]);
        acc[2] = fmaf(v, w0.z, acc[2]);
        acc[3] = fmaf(v, w0.w, acc[3]);
        acc[4] = fmaf(v, w1.x, acc[4]);
        acc[5] = fmaf(v, w1.y, acc[5]);
        acc[6] = fmaf(v, w1.z, acc[6]);
        acc[7] = fmaf(v, w1.w, acc[7]);
    }
    float4 o0, o1;
    o0.x=acc[0]; o0.y=acc[1]; o0.z=acc[2]; o0.w=acc[3];
    o1.x=acc[4]; o1.y=acc[5]; o1.z=acc[6]; o1.w=acc[7];
    *(float4*)(R + (size_t)row * DD + d0)     = o0;
    *(float4*)(R + (size_t)row * DD + d0 + 4) = o1;
}

// ---------------- launch ------------------------------------------------------
extern "C" void kernel_launch(void* const* d_in, const int* in_sizes, int n_in,
                              void* d_out, int out_size) {
    const float* X    = (const float*)d_in[0];  // [B, D]
    const float* W    = (const float*)d_in[1];  // [D, L]
    const float* benc = (const float*)d_in[2];  // [L]
    const float* bdec = (const float*)d_in[3];  // [D]

    float* recon = (float*)d_out;                       // [B, D]
    float* Zs    = (float*)d_out + (size_t)BB * DD;     // [B, L] z_sparse

    static int attr_set = 0;
    if (!attr_set) {
        cudaFuncSetAttribute(encode_gemm_mma,
                             cudaFuncAttributeMaxDynamicSharedMemorySize, GEMM_SMEM);
        attr_set = 1;
    }

    // 1) W -> Wt fp32 + W bf16 (single read of W)
    {
        dim3 grid(LL / 32, DD / 32);
        dim3 block(32, 8);
        transpose_kernel<<<grid, block>>>(W);
    }
    // 2) X -> bf16
    convert_x_kernel<<<(BB * DD / 4) / 256, 256>>>(X);
    // 3) approx encode GEMM on tensor cores -> |z_approx| half
    {
        dim3 grid(BB / BM, LL / BN);
        encode_gemm_mma<<<grid, 256, GEMM_SMEM>>>(benc);
    }
    // 4) zero z_sparse region
    cudaMemsetAsync(Zs, 0, (size_t)BB * LL * sizeof(float));
    // 5) select + exact recompute + topk + scatter + decode (fused, 1 block/row)
    finalize_kernel<<<BB, 256>>>(X, benc, bdec, Zs, recon);
}

// round 5
// speedup vs baseline: 1.1305x; 1.1305x over previous
#include <cuda_runtime.h>
#include <cuda_fp16.h>
#include <cuda_bf16.h>
#include <stdint.h>

// Problem dims (fixed)
#define BB 4096   // batch
#define DD 2048   // input dim
#define LL 16384  // latent dim
#define KK 64     // topk
#define CAND_MAX 512

// ---------------- scratch (static device globals) ---------------------------
__device__ float         g_Wt[(size_t)LL * DD];    // W^T fp32 [L, D]
__device__ __nv_bfloat16 g_WB[(size_t)DD * LL];    // W bf16  [D, L]
__device__ __nv_bfloat16 g_XB[(size_t)BB * DD];    // X bf16  [B, D]
__device__ __half        g_Zh[(size_t)BB * LL];    // |z_approx| half [B, L]

// ---------------- mma.sync helpers -------------------------------------------
__device__ __forceinline__ void cp16(uint32_t dst, const void* src) {
    asm volatile("cp.async.cg.shared.global [%0], [%1], 16;\n" :: "r"(dst), "l"(src));
}

__device__ __forceinline__ void ldsm_x4(uint32_t* r, uint32_t addr) {
    asm volatile("ldmatrix.sync.aligned.m8n8.x4.shared.b16 {%0,%1,%2,%3}, [%4];"
                 : "=r"(r[0]), "=r"(r[1]), "=r"(r[2]), "=r"(r[3]) : "r"(addr));
}

__device__ __forceinline__ void ldsm_x4_t(uint32_t* r, uint32_t addr) {
    asm volatile("ldmatrix.sync.aligned.m8n8.x4.trans.shared.b16 {%0,%1,%2,%3}, [%4];"
                 : "=r"(r[0]), "=r"(r[1]), "=r"(r[2]), "=r"(r[3]) : "r"(addr));
}

__device__ __forceinline__ void mma16816(float* c, const uint32_t* a, const uint32_t* b) {
    asm volatile(
        "mma.sync.aligned.m16n8k16.row.col.f32.bf16.bf16.f32 "
        "{%0,%1,%2,%3}, {%4,%5,%6,%7}, {%8,%9}, {%0,%1,%2,%3};"
        : "+f"(c[0]), "+f"(c[1]), "+f"(c[2]), "+f"(c[3])
        : "r"(a[0]), "r"(a[1]), "r"(a[2]), "r"(a[3]), "r"(b[0]), "r"(b[1]));
}

// ---------------- W transpose (fp32) + bf16 copy of W ------------------------
__global__ void transpose_kernel(const float* __restrict__ W) {
    __shared__ float tile[32][33];
    int l0 = blockIdx.x * 32;
    int d0 = blockIdx.y * 32;
    int tx = threadIdx.x;
    int ty = threadIdx.y;
    #pragma unroll
    for (int r = ty; r < 32; r += 8) {
        size_t src = (size_t)(d0 + r) * LL + (l0 + tx);
        float v = W[src];
        tile[r][tx] = v;
        g_WB[src] = __float2bfloat16(v);
    }
    __syncthreads();
    #pragma unroll
    for (int r = ty; r < 32; r += 8)
        g_Wt[(size_t)(l0 + r) * DD + (d0 + tx)] = tile[tx][r];
}

// ---------------- X -> bf16 ---------------------------------------------------
__global__ __launch_bounds__(256) void convert_x_kernel(const float* __restrict__ X) {
    size_t i = (size_t)blockIdx.x * 256 + threadIdx.x;
    float4 v = ((const float4*)X)[i];
    __nv_bfloat16 o[4];
    o[0] = __float2bfloat16(v.x);
    o[1] = __float2bfloat16(v.y);
    o[2] = __float2bfloat16(v.z);
    o[3] = __float2bfloat16(v.w);
    *(uint2*)(&g_XB[i * 4]) = *(uint2*)o;
}

// ---------------- encode GEMM: 128x128 block, BK=64, 3 stages, reg-pipelined -
#define BM 128
#define BN 128
#define BK 64
#define STG 3
#define ASTRIDE 72                  // 64+8 pad (bf16 elems)
#define BSTRIDE 136                 // 128+8 pad
#define ASTG_B (BM * ASTRIDE * 2)   // 18432
#define BSTG_B (BK * BSTRIDE * 2)   // 17408
#define GEMM_SMEM (STG * (ASTG_B + BSTG_B) + 1024)

__global__ __launch_bounds__(256) void encode_gemm_mma(const float* __restrict__ benc) {
    extern __shared__ unsigned char dynsm[];
    const uint32_t sbase = (uint32_t)__cvta_generic_to_shared(dynsm);
    const uint32_t sA = sbase;
    const uint32_t sB = sbase + STG * ASTG_B;
    float* sbias = (float*)(dynsm + STG * (ASTG_B + BSTG_B));

    const int tid = threadIdx.x;
    const int lane = tid & 31;
    const int wid = tid >> 5;
    const int warp_m = wid >> 1;     // 0..3 -> 32 rows
    const int warp_n = wid & 1;      // 0..1 -> 64 cols
    const int row0 = blockIdx.x * BM;
    const int n0   = blockIdx.y * BN;

    if (tid < BN) sbias[tid] = benc[n0 + tid];

    const int a_r = lane & 15;
    const int a_k = (lane >> 4) << 3;
    const int b_k = (lane & 7) + ((lane >> 3) & 1) * 8;
    const int b_n = (lane >> 4) << 3;

    auto load_stage = [&](int s, int buf) {
        const int k0 = s * BK;
        #pragma unroll
        for (int c = tid; c < 1024; c += 256) {      // A: 128 rows x 8 chunks of 8
            int r = c >> 3, col = (c & 7) * 8;
            cp16(sA + buf * ASTG_B + r * (ASTRIDE * 2) + col * 2,
                 g_XB + (size_t)(row0 + r) * DD + k0 + col);
        }
        #pragma unroll
        for (int c = tid; c < 1024; c += 256) {      // B: 64 rows x 16 chunks of 8
            int r = c >> 4, col = (c & 15) * 8;
            cp16(sB + buf * BSTG_B + r * (BSTRIDE * 2) + col * 2,
                 g_WB + (size_t)(k0 + r) * LL + n0 + col);
        }
    };

    #pragma unroll
    for (int s = 0; s < STG; s++) {
        load_stage(s, s);
        asm volatile("cp.async.commit_group;" ::: "memory");
    }

    float acc[2][8][4];
    #pragma unroll
    for (int i = 0; i < 2; i++)
        #pragma unroll
        for (int j = 0; j < 8; j++)
            #pragma unroll
            for (int q = 0; q < 4; q++) acc[i][j][q] = 0.0f;

    uint32_t ar[2][2][4], br[2][4][4];

    const int NST = DD / BK;   // 32
    for (int s = 0; s < NST; s++) {
        asm volatile("cp.async.wait_group %0;" :: "n"(STG - 1) : "memory");
        __syncthreads();
        const int buf = s % STG;
        const uint32_t a_base = sA + buf * ASTG_B;
        const uint32_t b_base = sB + buf * BSTG_B;

        // prefetch kk=0 fragments
        #pragma unroll
        for (int i = 0; i < 2; i++)
            ldsm_x4(ar[0][i], a_base + (warp_m * 32 + i * 16 + a_r) * (ASTRIDE * 2) + a_k * 2);
        #pragma unroll
        for (int j = 0; j < 4; j++)
            ldsm_x4_t(br[0][j], b_base + b_k * (BSTRIDE * 2)
                               + (warp_n * 64 + j * 16 + b_n) * 2);

        #pragma unroll
        for (int t = 0; t < 4; t++) {          // kk = 16*t
            const int cur = t & 1, nxt = cur ^ 1;
            if (t < 3) {
                const int kk = 16 * (t + 1);
                #pragma unroll
                for (int i = 0; i < 2; i++)
                    ldsm_x4(ar[nxt][i], a_base + (warp_m * 32 + i * 16 + a_r) * (ASTRIDE * 2)
                                       + (kk + a_k) * 2);
                #pragma unroll
                for (int j = 0; j < 4; j++)
                    ldsm_x4_t(br[nxt][j], b_base + (kk + b_k) * (BSTRIDE * 2)
                                         + (warp_n * 64 + j * 16 + b_n) * 2);
            }
            #pragma unroll
            for (int i = 0; i < 2; i++)
                #pragma unroll
                for (int j = 0; j < 8; j++)
                    mma16816(acc[i][j], ar[cur][i], &br[cur][j >> 1][(j & 1) * 2]);
        }
        __syncthreads();
        if (s + STG < NST) load_stage(s + STG, buf);
        asm volatile("cp.async.commit_group;" ::: "memory");
    }

    // epilogue: z = acc + bias; store |z| as half
    #pragma unroll
    for (int i = 0; i < 2; i++) {
        const int r_lo = row0 + warp_m * 32 + i * 16 + (lane >> 2);
        #pragma unroll
        for (int j = 0; j < 8; j++) {
            const int cl = warp_n * 64 + j * 8 + (lane & 3) * 2;
            float z0 = fabsf(acc[i][j][0] + sbias[cl]);
            float z1 = fabsf(acc[i][j][1] + sbias[cl + 1]);
            float z2 = fabsf(acc[i][j][2] + sbias[cl]);
            float z3 = fabsf(acc[i][j][3] + sbias[cl + 1]);
            *(__half2*)(g_Zh + (size_t)r_lo * LL + n0 + cl)       = __floats2half2_rn(z0, z1);
            *(__half2*)(g_Zh + (size_t)(r_lo + 8) * LL + n0 + cl) = __floats2half2_rn(z2, z3);
        }
    }
}

// ---------------- finalize: zero + select + exact recompute + topk + decode --
// One block (512 threads) per row.
__global__ __launch_bounds__(512) void finalize_kernel(
    const float* __restrict__ X, const float* __restrict__ benc,
    const float* __restrict__ bdec, float* __restrict__ Zs,
    float* __restrict__ R)
{
    __shared__ unsigned short keys[LL];     // 32 KB
    __shared__ float sx[DD];                // 8 KB
    __shared__ float sval[CAND_MAX];
    __shared__ int   scid[CAND_MAX];
    __shared__ float sv64[KK];
    __shared__ int   si64[KK];
    __shared__ int   hist[256];
    __shared__ int   s_h, s_rem, s_ctk, s_cnt, s_pos;

    const int row = blockIdx.x;
    const int tid = threadIdx.x;
    const int lid = tid & 31, wid = tid >> 5;   // 16 warps

    // zero-fill z_sparse row (replaces global memset)
    float4 zf; zf.x = zf.y = zf.z = zf.w = 0.0f;
    float4* zrow4 = (float4*)(Zs + (size_t)row * LL);
    #pragma unroll
    for (int i = 0; i < 8; i++) zrow4[tid + i * 512] = zf;

    // load |z| keys + x row
    const __half* zr = g_Zh + (size_t)row * LL;
    #pragma unroll
    for (int i = 0; i < 4; i++) {
        int v4 = tid + i * 512;
        ((uint4*)keys)[v4] = ((const uint4*)zr)[v4];
    }
    ((float4*)sx)[tid] = ((const float4*)(X + (size_t)row * DD))[tid];
    if (tid == 0) { s_cnt = 0; s_pos = 0; }
    if (tid < 256) hist[tid] = 0;
    __syncthreads();

    // radix pass 1: high byte
    #pragma unroll 4
    for (int i = 0; i < 32; i++) {
        unsigned k = keys[tid + i * 512];
        atomicAdd(&hist[k >> 8], 1);
    }
    __syncthreads();
    if (tid == 0) {
        int r = KK;
        for (int b = 255; b >= 0; b--) {
            int c = hist[b];
            if (c >= r) { s_h = b; s_rem = r; break; }
            r -= c;
        }
    }
    __syncthreads();
    const unsigned hb = (unsigned)s_h;
    if (tid < 256) hist[tid] = 0;
    __syncthreads();

    // radix pass 2: low byte
    #pragma unroll 4
    for (int i = 0; i < 32; i++) {
        unsigned k = keys[tid + i * 512];
        if ((k >> 8) == hb) atomicAdd(&hist[k & 255], 1);
    }
    __syncthreads();
    if (tid == 0) {
        int r = s_rem; int lo = 0;
        for (int b = 255; b >= 0; b--) {
            int c = hist[b];
            if (c >= r) { lo = b; break; }
            r -= c;
        }
        unsigned short t64 = (unsigned short)((hb << 8) | (unsigned)lo);
        float tf = __half2float(__ushort_as_half(t64));
        float thr = fmaxf(tf - 0.09f, 0.0f);     // margin >> bf16 GEMM noise
        s_ctk = (int)(unsigned)__half_as_ushort(__float2half_rd(thr));
    }
    __syncthreads();
    const unsigned ctk = (unsigned)s_ctk;

    // collect candidates
    #pragma unroll 4
    for (int i = 0; i < 32; i++) {
        int idx = tid + i * 512;
        if ((unsigned)keys[idx] >= ctk) {
            int p = atomicAdd(&s_cnt, 1);
            if (p < CAND_MAX) scid[p] = idx;
        }
    }
    __syncthreads();
    const int nc = min(s_cnt, CAND_MAX);

    // exact fp32 dot per candidate (warp per candidate, 16 warps)
    for (int c = wid; c < nc; c += 16) {
        int idx = scid[c];
        const float* wp = g_Wt + (size_t)idx * DD;
        float acc = 0.0f;
        #pragma unroll 8
        for (int i = 0; i < DD / 32; i++)
            acc = fmaf(wp[lid + i * 32], sx[lid + i * 32], acc);
        #pragma unroll
        for (int o = 16; o > 0; o >>= 1)
            acc += __shfl_down_sync(0xffffffffu, acc, o);
        if (lid == 0) sval[c] = acc + benc[idx];
    }
    __syncthreads();

    // exact rank among candidates (|v| desc, lowest index wins on ties)
    for (int c = tid; c < nc; c += 512) {
        float v = sval[c];
        float av = fabsf(v);
        int id = scid[c];
        int rank = 0;
        for (int j = 0; j < nc; j++) {
            float aj = fabsf(sval[j]);
            if (aj > av || (aj == av && scid[j] < id)) rank++;
        }
        if (rank < KK) {
            int p = atomicAdd(&s_pos, 1);
            si64[p] = id;
            sv64[p] = v;
            Zs[(size_t)row * LL + id] = v;
        }
    }
    __syncthreads();
    const int nsel = s_pos;

    // decode: recon[row, :] = sum_j v_j * Wt[idx_j, :] + b_dec
    const int d0 = tid * 4;   // 512 * 4 = 2048
    float acc[4];
    {
        float4 b0 = *(const float4*)(bdec + d0);
        acc[0] = b0.x; acc[1] = b0.y; acc[2] = b0.z; acc[3] = b0.w;
    }
    for (int j = 0; j < nsel; j++) {
        const float v = sv64[j];
        float4 w0 = *(const float4*)(g_Wt + (size_t)si64[j] * DD + d0);
        acc[0] = fmaf(v, w0.x, acc[0]);
        acc[1] = fmaf(v, w0.y, acc[1]);
        acc[2] = fmaf(v, w0.z, acc[2]);
        acc[3] = fmaf(v, w0.w, acc[3]);
    }
    float4 o0;
    o0.x = acc[0]; o0.y = acc[1]; o0.z = acc[2]; o0.w = acc[3];
    *(float4*)(R + (size_t)row * DD + d0) = o0;
}

// ---------------- launch ------------------------------------------------------
extern "C" void kernel_launch(void* const* d_in, const int* in_sizes, int n_in,
                              void* d_out, int out_size) {
    const float* X    = (const float*)d_in[0];  // [B, D]
    const float* W    = (const float*)d_in[1];  // [D, L]
    const float* benc = (const float*)d_in[2];  // [L]
    const float* bdec = (const float*)d_in[3];  // [D]

    float* recon = (float*)d_out;                       // [B, D]
    float* Zs    = (float*)d_out + (size_t)BB * DD;     // [B, L] z_sparse

    static int attr_set = 0;
    if (!attr_set) {
        cudaFuncSetAttribute(encode_gemm_mma,
                             cudaFuncAttributeMaxDynamicSharedMemorySize, GEMM_SMEM);
        attr_set = 1;
    }

    // 1) W -> Wt fp32 + W bf16 (single read of W)
    {
        dim3 grid(LL / 32, DD / 32);
        dim3 block(32, 8);
        transpose_kernel<<<grid, block>>>(W);
    }
    // 2) X -> bf16
    convert_x_kernel<<<(BB * DD / 4) / 256, 256>>>(X);
    // 3) approx encode GEMM on tensor cores -> |z_approx| half
    {
        dim3 grid(BB / BM, LL / BN);
        encode_gemm_mma<<<grid, 256, GEMM_SMEM>>>(benc);
    }
    // 4) fused: zero + select + exact recompute + topk + scatter + decode
    finalize_kernel<<<BB, 512>>>(X, benc, bdec, Zs, recon);
}

// round 7
// speedup vs baseline: 1.2011x; 1.0624x over previous
#include <cuda_runtime.h>
#include <cuda_fp16.h>
#include <cuda_bf16.h>
#include <stdint.h>

// Problem dims (fixed)
#define BB 4096   // batch
#define DD 2048   // input dim
#define LL 16384  // latent dim
#define KK 64     // topk
#define CAND_MAX 512

// ---------------- scratch (static device globals) ---------------------------
__device__ float         g_Wt[(size_t)LL * DD];    // W^T fp32 [L, D]
__device__ __nv_bfloat16 g_WB[(size_t)DD * LL];    // W bf16  [D, L]
__device__ __nv_bfloat16 g_XB[(size_t)BB * DD];    // X bf16  [B, D]
__device__ __half        g_Zh[(size_t)BB * LL];    // |z_approx| half [B, L]

// ---------------- mma.sync helpers -------------------------------------------
__device__ __forceinline__ void cp16(uint32_t dst, const void* src) {
    asm volatile("cp.async.cg.shared.global [%0], [%1], 16;\n" :: "r"(dst), "l"(src));
}

__device__ __forceinline__ void ldsm_x4(uint32_t* r, uint32_t addr) {
    asm volatile("ldmatrix.sync.aligned.m8n8.x4.shared.b16 {%0,%1,%2,%3}, [%4];"
                 : "=r"(r[0]), "=r"(r[1]), "=r"(r[2]), "=r"(r[3]) : "r"(addr));
}

__device__ __forceinline__ void ldsm_x4_t(uint32_t* r, uint32_t addr) {
    asm volatile("ldmatrix.sync.aligned.m8n8.x4.trans.shared.b16 {%0,%1,%2,%3}, [%4];"
                 : "=r"(r[0]), "=r"(r[1]), "=r"(r[2]), "=r"(r[3]) : "r"(addr));
}

__device__ __forceinline__ void mma16816(float* c, const uint32_t* a, const uint32_t* b) {
    asm volatile(
        "mma.sync.aligned.m16n8k16.row.col.f32.bf16.bf16.f32 "
        "{%0,%1,%2,%3}, {%4,%5,%6,%7}, {%8,%9}, {%0,%1,%2,%3};"
        : "+f"(c[0]), "+f"(c[1]), "+f"(c[2]), "+f"(c[3])
        : "r"(a[0]), "r"(a[1]), "r"(a[2]), "r"(a[3]), "r"(b[0]), "r"(b[1]));
}

// ---------------- W transpose (fp32) + bf16 copy of W ------------------------
__global__ void transpose_kernel(const float* __restrict__ W) {
    __shared__ float tile[32][33];
    int l0 = blockIdx.x * 32;
    int d0 = blockIdx.y * 32;
    int tx = threadIdx.x;
    int ty = threadIdx.y;
    #pragma unroll
    for (int r = ty; r < 32; r += 8) {
        size_t src = (size_t)(d0 + r) * LL + (l0 + tx);
        float v = W[src];
        tile[r][tx] = v;
        g_WB[src] = __float2bfloat16(v);
    }
    __syncthreads();
    #pragma unroll
    for (int r = ty; r < 32; r += 8)
        g_Wt[(size_t)(l0 + r) * DD + (d0 + tx)] = tile[tx][r];
}

// ---------------- X -> bf16 ---------------------------------------------------
__global__ __launch_bounds__(256) void convert_x_kernel(const float* __restrict__ X) {
    size_t i = (size_t)blockIdx.x * 256 + threadIdx.x;
    float4 v = ((const float4*)X)[i];
    __nv_bfloat16 o[4];
    o[0] = __float2bfloat16(v.x);
    o[1] = __float2bfloat16(v.y);
    o[2] = __float2bfloat16(v.z);
    o[3] = __float2bfloat16(v.w);
    *(uint2*)(&g_XB[i * 4]) = *(uint2*)o;
}

// ---------------- encode GEMM: 128x128 block, BK=64, 3 stages, reg-pipelined -
#define BM 128
#define BN 128
#define BK 64
#define STG 3
#define ASTRIDE 72                  // 64+8 pad (bf16 elems)
#define BSTRIDE 136                 // 128+8 pad
#define ASTG_B (BM * ASTRIDE * 2)   // 18432
#define BSTG_B (BK * BSTRIDE * 2)   // 17408
#define GEMM_SMEM (STG * (ASTG_B + BSTG_B) + 1024)

__global__ __launch_bounds__(256) void encode_gemm_mma(const float* __restrict__ benc) {
    extern __shared__ unsigned char dynsm[];
    const uint32_t sbase = (uint32_t)__cvta_generic_to_shared(dynsm);
    const uint32_t sA = sbase;
    const uint32_t sB = sbase + STG * ASTG_B;
    float* sbias = (float*)(dynsm + STG * (ASTG_B + BSTG_B));

    const int tid = threadIdx.x;
    const int lane = tid & 31;
    const int wid = tid >> 5;
    const int warp_m = wid >> 1;     // 0..3 -> 32 rows
    const int warp_n = wid & 1;      // 0..1 -> 64 cols
    const int row0 = blockIdx.x * BM;
    const int n0   = blockIdx.y * BN;

    if (tid < BN) sbias[tid] = benc[n0 + tid];

    const int a_r = lane & 15;
    const int a_k = (lane >> 4) << 3;
    const int b_k = (lane & 7) + ((lane >> 3) & 1) * 8;
    const int b_n = (lane >> 4) << 3;

    auto load_stage = [&](int s, int buf) {
        const int k0 = s * BK;
        #pragma unroll
        for (int c = tid; c < 1024; c += 256) {      // A: 128 rows x 8 chunks of 8
            int r = c >> 3, col = (c & 7) * 8;
            cp16(sA + buf * ASTG_B + r * (ASTRIDE * 2) + col * 2,
                 g_XB + (size_t)(row0 + r) * DD + k0 + col);
        }
        #pragma unroll
        for (int c = tid; c < 1024; c += 256) {      // B: 64 rows x 16 chunks of 8
            int r = c >> 4, col = (c & 15) * 8;
            cp16(sB + buf * BSTG_B + r * (BSTRIDE * 2) + col * 2,
                 g_WB + (size_t)(k0 + r) * LL + n0 + col);
        }
    };

    #pragma unroll
    for (int s = 0; s < STG; s++) {
        load_stage(s, s);
        asm volatile("cp.async.commit_group;" ::: "memory");
    }

    float acc[2][8][4];
    #pragma unroll
    for (int i = 0; i < 2; i++)
        #pragma unroll
        for (int j = 0; j < 8; j++)
            #pragma unroll
            for (int q = 0; q < 4; q++) acc[i][j][q] = 0.0f;

    uint32_t ar[2][2][4], br[2][4][4];

    const int NST = DD / BK;   // 32
    for (int s = 0; s < NST; s++) {
        asm volatile("cp.async.wait_group %0;" :: "n"(STG - 1) : "memory");
        __syncthreads();
        const int buf = s % STG;
        const uint32_t a_base = sA + buf * ASTG_B;
        const uint32_t b_base = sB + buf * BSTG_B;

        // prefetch kk=0 fragments
        #pragma unroll
        for (int i = 0; i < 2; i++)
            ldsm_x4(ar[0][i], a_base + (warp_m * 32 + i * 16 + a_r) * (ASTRIDE * 2) + a_k * 2);
        #pragma unroll
        for (int j = 0; j < 4; j++)
            ldsm_x4_t(br[0][j], b_base + b_k * (BSTRIDE * 2)
                               + (warp_n * 64 + j * 16 + b_n) * 2);

        #pragma unroll
        for (int t = 0; t < 4; t++) {          // kk = 16*t
            const int cur = t & 1, nxt = cur ^ 1;
            if (t < 3) {
                const int kk = 16 * (t + 1);
                #pragma unroll
                for (int i = 0; i < 2; i++)
                    ldsm_x4(ar[nxt][i], a_base + (warp_m * 32 + i * 16 + a_r) * (ASTRIDE * 2)
                                       + (kk + a_k) * 2);
                #pragma unroll
                for (int j = 0; j < 4; j++)
                    ldsm_x4_t(br[nxt][j], b_base + (kk + b_k) * (BSTRIDE * 2)
                                         + (warp_n * 64 + j * 16 + b_n) * 2);
            }
            #pragma unroll
            for (int i = 0; i < 2; i++)
                #pragma unroll
                for (int j = 0; j < 8; j++)
                    mma16816(acc[i][j], ar[cur][i], &br[cur][j >> 1][(j & 1) * 2]);
        }
        __syncthreads();
        if (s + STG < NST) load_stage(s + STG, buf);
        asm volatile("cp.async.commit_group;" ::: "memory");
    }

    // epilogue: z = acc + bias; store |z| as half
    #pragma unroll
    for (int i = 0; i < 2; i++) {
        const int r_lo = row0 + warp_m * 32 + i * 16 + (lane >> 2);
        #pragma unroll
        for (int j = 0; j < 8; j++) {
            const int cl = warp_n * 64 + j * 8 + (lane & 3) * 2;
            float z0 = fabsf(acc[i][j][0] + sbias[cl]);
            float z1 = fabsf(acc[i][j][1] + sbias[cl + 1]);
            float z2 = fabsf(acc[i][j][2] + sbias[cl]);
            float z3 = fabsf(acc[i][j][3] + sbias[cl + 1]);
            *(__half2*)(g_Zh + (size_t)r_lo * LL + n0 + cl)       = __floats2half2_rn(z0, z1);
            *(__half2*)(g_Zh + (size_t)(r_lo + 8) * LL + n0 + cl) = __floats2half2_rn(z2, z3);
        }
    }
}

// ---------------- finalize: zero + select + exact recompute + topk + decode --
// One block (512 threads) per row. Candidate dots: half-warp per candidate,
// float4 gathers; UNIFORM trip count + half-warp shuffle masks (no divergence
// hazard across half-warps of the same warp).
__global__ __launch_bounds__(512) void finalize_kernel(
    const float* __restrict__ X, const float* __restrict__ benc,
    const float* __restrict__ bdec, float* __restrict__ Zs,
    float* __restrict__ R)
{
    __shared__ unsigned short keys[LL];     // 32 KB
    __shared__ float sx[DD];                // 8 KB
    __shared__ float sval[CAND_MAX];
    __shared__ int   scid[CAND_MAX];
    __shared__ float sv64[KK];
    __shared__ int   si64[KK];
    __shared__ int   hist[256];
    __shared__ int   s_h, s_rem, s_ctk, s_cnt, s_pos;

    const int row = blockIdx.x;
    const int tid = threadIdx.x;
    const int lid = tid & 31;
    const int hw  = tid >> 4;                   // half-warp id 0..31
    const int hl  = tid & 15;                   // lane within half-warp
    const unsigned hmask = 0xFFFFu << ((lid >> 4) << 4);  // this half-warp's lanes

    // zero-fill z_sparse row (replaces global memset)
    float4 zf; zf.x = zf.y = zf.z = zf.w = 0.0f;
    float4* zrow4 = (float4*)(Zs + (size_t)row * LL);
    #pragma unroll
    for (int i = 0; i < 8; i++) zrow4[tid + i * 512] = zf;

    // load |z| keys + x row
    const __half* zr = g_Zh + (size_t)row * LL;
    #pragma unroll
    for (int i = 0; i < 4; i++) {
        int v4 = tid + i * 512;
        ((uint4*)keys)[v4] = ((const uint4*)zr)[v4];
    }
    ((float4*)sx)[tid] = ((const float4*)(X + (size_t)row * DD))[tid];
    if (tid == 0) { s_cnt = 0; s_pos = 0; }
    if (tid < 256) hist[tid] = 0;
    __syncthreads();

    // radix pass 1: high byte
    #pragma unroll 4
    for (int i = 0; i < 32; i++) {
        unsigned k = keys[tid + i * 512];
        atomicAdd(&hist[k >> 8], 1);
    }
    __syncthreads();
    if (tid == 0) {
        int r = KK;
        for (int b = 255; b >= 0; b--) {
            int c = hist[b];
            if (c >= r) { s_h = b; s_rem = r; break; }
            r -= c;
        }
    }
    __syncthreads();
    const unsigned hb = (unsigned)s_h;
    if (tid < 256) hist[tid] = 0;
    __syncthreads();

    // radix pass 2: low byte
    #pragma unroll 4
    for (int i = 0; i < 32; i++) {
        unsigned k = keys[tid + i * 512];
        if ((k >> 8) == hb) atomicAdd(&hist[k & 255], 1);
    }
    __syncthreads();
    if (tid == 0) {
        int r = s_rem; int lo = 0;
        for (int b = 255; b >= 0; b--) {
            int c = hist[b];
            if (c >= r) { lo = b; break; }
            r -= c;
        }
        unsigned short t64 = (unsigned short)((hb << 8) | (unsigned)lo);
        float tf = __half2float(__ushort_as_half(t64));
        float thr = fmaxf(tf - 0.05f, 0.0f);     // margin ~17 sigma of bf16 GEMM noise
        s_ctk = (int)(unsigned)__half_as_ushort(__float2half_rd(thr));
    }
    __syncthreads();
    const unsigned ctk = (unsigned)s_ctk;

    // collect candidates
    #pragma unroll 4
    for (int i = 0; i < 32; i++) {
        int idx = tid + i * 512;
        if ((unsigned)keys[idx] >= ctk) {
            int p = atomicAdd(&s_cnt, 1);
            if (p < CAND_MAX) scid[p] = idx;
        }
    }
    __syncthreads();
    const int nc = min(s_cnt, CAND_MAX);

    // exact fp32 dot per candidate: one half-warp per candidate, float4 loads.
    // Uniform trip count across the whole block; predicated tail.
    const int iters = (nc + 31) >> 5;
    for (int it = 0; it < iters; it++) {
        const int c = hw + it * 32;
        const bool live = (c < nc);
        const int idx = live ? scid[c] : scid[0];
        const float4* wp = (const float4*)(g_Wt + (size_t)idx * DD);
        const float4* xp = (const float4*)sx;
        float acc = 0.0f;
        #pragma unroll 4
        for (int i = 0; i < DD / 64; i++) {     // 32 float4s per lane
            float4 w = wp[hl + i * 16];
            float4 x = xp[hl + i * 16];
            acc = fmaf(w.x, x.x, acc);
            acc = fmaf(w.y, x.y, acc);
            acc = fmaf(w.z, x.z, acc);
            acc = fmaf(w.w, x.w, acc);
        }
        #pragma unroll
        for (int o = 8; o > 0; o >>= 1)
            acc += __shfl_down_sync(hmask, acc, o, 16);
        if (hl == 0 && live) sval[c] = acc + benc[idx];
    }
    __syncthreads();

    // exact rank among candidates (|v| desc, lowest index wins on ties)
    for (int c = tid; c < nc; c += 512) {
        float v = sval[c];
        float av = fabsf(v);
        int id = scid[c];
        int rank = 0;
        for (int j = 0; j < nc; j++) {
            float aj = fabsf(sval[j]);
            if (aj > av || (aj == av && scid[j] < id)) rank++;
        }
        if (rank < KK) {
            int p = atomicAdd(&s_pos, 1);
            si64[p] = id;
            sv64[p] = v;
            Zs[(size_t)row * LL + id] = v;
        }
    }
    __syncthreads();
    const int nsel = s_pos;

    // decode: recon[row, :] = sum_j v_j * Wt[idx_j, :] + b_dec
    const int d0 = tid * 4;   // 512 * 4 = 2048
    float acc[4];
    {
        float4 b0 = *(const float4*)(bdec + d0);
        acc[0] = b0.x; acc[1] = b0.y; acc[2] = b0.z; acc[3] = b0.w;
    }
    for (int j = 0; j < nsel; j++) {
        const float v = sv64[j];
        float4 w0 = *(const float4*)(g_Wt + (size_t)si64[j] * DD + d0);
        acc[0] = fmaf(v, w0.x, acc[0]);
        acc[1] = fmaf(v, w0.y, acc[1]);
        acc[2] = fmaf(v, w0.z, acc[2]);
        acc[3] = fmaf(v, w0.w, acc[3]);
    }
    float4 o0;
    o0.x = acc[0]; o0.y = acc[1]; o0.z = acc[2]; o0.w = acc[3];
    *(float4*)(R + (size_t)row * DD + d0) = o0;
}

// ---------------- launch ------------------------------------------------------
extern "C" void kernel_launch(void* const* d_in, const int* in_sizes, int n_in,
                              void* d_out, int out_size) {
    const float* X    = (const float*)d_in[0];  // [B, D]
    const float* W    = (const float*)d_in[1];  // [D, L]
    const float* benc = (const float*)d_in[2];  // [L]
    const float* bdec = (const float*)d_in[3];  // [D]

    float* recon = (float*)d_out;                       // [B, D]
    float* Zs    = (float*)d_out + (size_t)BB * DD;     // [B, L] z_sparse

    static int attr_set = 0;
    if (!attr_set) {
        cudaFuncSetAttribute(encode_gemm_mma,
                             cudaFuncAttributeMaxDynamicSharedMemorySize, GEMM_SMEM);
        attr_set = 1;
    }

    // 1) W -> Wt fp32 + W bf16 (single read of W)
    {
        dim3 grid(LL / 32, DD / 32);
        dim3 block(32, 8);
        transpose_kernel<<<grid, block>>>(W);
    }
    // 2) X -> bf16
    convert_x_kernel<<<(BB * DD / 4) / 256, 256>>>(X);
    // 3) approx encode GEMM on tensor cores -> |z_approx| half
    {
        dim3 grid(BB / BM, LL / BN);
        encode_gemm_mma<<<grid, 256, GEMM_SMEM>>>(benc);
    }
    // 4) fused: zero + select + exact recompute + topk + scatter + decode
    finalize_kernel<<<BB, 512>>>(X, benc, bdec, Zs, recon);
}